// round 9
// baseline (speedup 1.0000x reference)
#include <cuda_runtime.h>
#include <cuda_fp16.h>
#include <cstdint>

// ============================================================================
// VersorLinear == one 4096x4096x4096 GEMM (Cayley folded into W) + fused
// per-32-column multivector normalization.
//   Y[b, o*32+k] = sum_{f,i} X[b, f*32+i] * sign(i, i^k) * W[o, f, i^k]
// fp16 operands (packed from fp32), fp32 accumulation via mma.sync HMMA.
// (tcgen05 unavailable: toolchain targets plain sm_103, no 'a' features.)
//
// R8: keep R7's winning shape (CTA 128x128, 4 warps of 64x64, 2 CTAs/SM) and
// attack loop overhead: BK=64 (64 iterations instead of 128), 3 stages,
// ONE __syncthreads per iteration (bottom barrier was redundant), and
// register double-buffering of ldmatrix fragments across the 4 ks sub-steps.
// ============================================================================

#define BATCH 4096
#define KDIM 4096
#define NDIM 4096

#define BM 128
#define BN 128
#define BK 64
#define KT (KDIM / BK)          // 64 k-iterations
#define STAGES 3
#define LDS 72                  // padded halves per smem row (144 B; stride 36
                                // words == 4 mod 32 -> conflict-free phases)
#define A_TILE_HALVES (BM * LDS)            // 9216
#define B_TILE_HALVES (BN * LDS)            // 9216
#define STAGE_HALVES (A_TILE_HALVES + B_TILE_HALVES)
#define SMEM_BYTES (STAGES * STAGE_HALVES * 2)   // 110592

// fp16-packed operands (scratch; __device__ globals per harness rules)
static __device__ __half g_Xh[(size_t)BATCH * KDIM];
static __device__ __half g_Wp[(size_t)NDIM * KDIM];

// ============================================================================
// helpers
// ============================================================================
__device__ __forceinline__ uint32_t smem_to_u32(const void* smem_ptr) {
    uint32_t addr;
    asm("{ .reg .u64 tmp; cvta.to.shared.u64 tmp, %1; cvt.u32.u64 %0, tmp; }"
        : "=r"(addr) : "l"(smem_ptr));
    return addr;
}

__device__ __forceinline__ void cp_async16(uint32_t saddr, const void* gaddr) {
    asm volatile("cp.async.cg.shared.global [%0], [%1], 16;"
                 :: "r"(saddr), "l"(gaddr) : "memory");
}

__device__ __forceinline__ void ldsm_x4(uint32_t* r, uint32_t addr) {
    asm volatile("ldmatrix.sync.aligned.m8n8.x4.shared.b16 {%0,%1,%2,%3}, [%4];"
                 : "=r"(r[0]), "=r"(r[1]), "=r"(r[2]), "=r"(r[3]) : "r"(addr));
}

__device__ __forceinline__ void mma16816(float* c, const uint32_t* a, const uint32_t* b) {
    asm volatile(
        "mma.sync.aligned.m16n8k16.row.col.f32.f16.f16.f32 "
        "{%0,%1,%2,%3}, {%4,%5,%6,%7}, {%8,%9}, {%0,%1,%2,%3};"
        : "+f"(c[0]), "+f"(c[1]), "+f"(c[2]), "+f"(c[3])
        : "r"(a[0]), "r"(a[1]), "r"(a[2]), "r"(a[3]), "r"(b[0]), "r"(b[1]));
}

// ============================================================================
// Cayley sign for Cl(4,1): sig = [1,1,1,1,-1] (only generator e4 negative)
// ============================================================================
__device__ __forceinline__ float cayley_sign(int a, int b) {
    int s = 0;
    int aa = a >> 1;
    while (aa) { s += __popc(aa & b); aa >>= 1; }
    s += ((a & b) >> 4) & 1;        // metric: -1 for shared generator e4
    return (s & 1) ? -1.0f : 1.0f;
}

// ============================================================================
// Pack kernels: fp32 -> fp16; W gets Cayley signs + blade permutation folded
//   Wp[o*32+k, f*32+i] = sign(i, i^k) * W[o, f, i^k]
// ============================================================================
__global__ void pack_x_kernel(const float* __restrict__ x) {
    size_t i4 = (size_t)blockIdx.x * blockDim.x + threadIdx.x;  // over float4
    float4 v = reinterpret_cast<const float4*>(x)[i4];
    __half2 h0 = __floats2half2_rn(v.x, v.y);
    __half2 h1 = __floats2half2_rn(v.z, v.w);
    uint2 pk;
    pk.x = *reinterpret_cast<uint32_t*>(&h0);
    pk.y = *reinterpret_cast<uint32_t*>(&h1);
    reinterpret_cast<uint2*>(g_Xh)[i4] = pk;
}

__global__ void pack_w_kernel(const float* __restrict__ w) {
    size_t idx2 = (size_t)blockIdx.x * blockDim.x + threadIdx.x;  // 8.39M pairs
    size_t idx = idx2 * 2;
    int kk = (int)(idx & 4095);          // column index (f*32+i)
    int n  = (int)(idx >> 12);           // row index (o*32+k)
    int i = kk & 31, f = kk >> 5;
    int kga = n & 31, o = n >> 5;
    const float* wrow = w + ((size_t)(o * 128 + f)) * 32;
    int j0 = i ^ kga, j1 = (i + 1) ^ kga;
    float v0 = cayley_sign(i, j0) * wrow[j0];
    float v1 = cayley_sign(i + 1, j1) * wrow[j1];
    __half2 h = __floats2half2_rn(v0, v1);
    reinterpret_cast<__half2*>(g_Wp)[idx2] = h;
}

// ============================================================================
// GEMM kernel: Y = Xh @ Wp^T with fused multivector normalization.
// 128 threads = 4 warps (2 m x 2 n), warp tile 64x64, 3-stage cp.async BK=64,
// 2 CTAs/SM, single barrier per k-iteration, fragment double buffering.
// ============================================================================
__global__ void __launch_bounds__(128, 2) versor_gemm_kernel(float* __restrict__ out) {
    extern __shared__ __half smem[];
    const uint32_t sb = smem_to_u32(smem);

    const int tid  = threadIdx.x;
    const int lane = tid & 31;
    const int wid  = tid >> 5;     // 0..3
    const int wm   = wid >> 1;     // 0..1
    const int wn   = wid & 1;      // 0..1

    // supertile raster: 8 m-tiles per group, sweep n within group (L2 reuse)
    const int TN = NDIM / BN;      // 32
    const int GM = 8;
    int bid   = blockIdx.x;        // 0..1023
    int group = bid / (GM * TN);   // 0..3
    int tm    = group * GM + (bid % GM);
    int tn    = (bid % (GM * TN)) / GM;

    const __half* Abase = g_Xh + ((size_t)tm * BM) * KDIM;
    const __half* Bbase = g_Wp + ((size_t)tn * BN) * KDIM;

    // loader mapping: 16B chunks, 8 chunks/row (BK=64 halves).
    // A tile: 1024 chunks; thread t does chunks {t + i*128}, i=0..7.
    const int lrow = tid >> 3;             // 0..15
    const int lcol = (tid & 7) * 8;        // halves 0..56

    // ---- prefetch STAGES-1 stages
    #pragma unroll
    for (int s = 0; s < STAGES - 1; s++) {
        uint32_t sa  = sb + (s * STAGE_HALVES) * 2;
        uint32_t sbm = sa + A_TILE_HALVES * 2;
        const __half* Ak = Abase + s * BK;
        const __half* Bk = Bbase + s * BK;
        #pragma unroll
        for (int i = 0; i < 8; i++) {
            int row = lrow + i * 16;
            cp_async16(sa  + (row * LDS + lcol) * 2, Ak + (size_t)row * KDIM + lcol);
            cp_async16(sbm + (row * LDS + lcol) * 2, Bk + (size_t)row * KDIM + lcol);
        }
        asm volatile("cp.async.commit_group;" ::: "memory");
    }

    float c[4][8][4];
    #pragma unroll
    for (int mt = 0; mt < 4; mt++)
        #pragma unroll
        for (int nt = 0; nt < 8; nt++)
            #pragma unroll
            for (int j = 0; j < 4; j++) c[mt][nt][j] = 0.0f;

    // ldmatrix lane addressing (constant across k-iterations)
    const int a_row_l = lane & 15;
    const int a_colg  = ((lane >> 4) & 1) * 8;
    const int b_row_l = (lane & 7) + ((lane & 16) >> 1);
    const int b_colg  = lane & 8;

    const uint32_t a_lane_off = (uint32_t)((wm * 64 + a_row_l) * LDS + a_colg) * 2;
    const uint32_t b_lane_off = (uint32_t)((wn * 64 + b_row_l) * LDS + b_colg) * 2;

    uint32_t af[2][4][4], bf[2][4][4];

    for (int kt = 0; kt < KT; kt++) {
        asm volatile("cp.async.wait_group %0;" :: "n"(STAGES - 2) : "memory");
        __syncthreads();   // single barrier: orders kt-1 reads before overwrite

        // issue loads for stage kt+STAGES-1 (into the slot just consumed)
        int lt = kt + STAGES - 1;
        if (lt < KT) {
            int slot = lt % STAGES;
            uint32_t sa  = sb + (slot * STAGE_HALVES) * 2;
            uint32_t sbm = sa + A_TILE_HALVES * 2;
            const __half* Ak = Abase + lt * BK;
            const __half* Bk = Bbase + lt * BK;
            #pragma unroll
            for (int i = 0; i < 8; i++) {
                int row = lrow + i * 16;
                cp_async16(sa  + (row * LDS + lcol) * 2, Ak + (size_t)row * KDIM + lcol);
                cp_async16(sbm + (row * LDS + lcol) * 2, Bk + (size_t)row * KDIM + lcol);
            }
        }
        asm volatile("cp.async.commit_group;" ::: "memory");

        // ---- compute on stage kt: 4 ks sub-steps (K=16 each), frags
        // double-buffered so LDSM(ks+1) overlaps MMA(ks).
        int slot = kt % STAGES;
        uint32_t aoff = sb + (slot * STAGE_HALVES) * 2 + a_lane_off;
        uint32_t boff = sb + (slot * STAGE_HALVES) * 2 + A_TILE_HALVES * 2 + b_lane_off;

        // prime ks=0
        #pragma unroll
        for (int mt = 0; mt < 4; mt++)
            ldsm_x4(af[0][mt], aoff + (mt * 16 * LDS) * 2);
        #pragma unroll
        for (int bt = 0; bt < 4; bt++)
            ldsm_x4(bf[0][bt], boff + (bt * 16 * LDS) * 2);

        #pragma unroll
        for (int ks = 0; ks < 4; ks++) {
            int cur = ks & 1, nxt = cur ^ 1;
            if (ks < 3) {
                uint32_t acol = aoff + ((ks + 1) * 16) * 2;
                uint32_t bcol = boff + ((ks + 1) * 16) * 2;
                #pragma unroll
                for (int mt = 0; mt < 4; mt++)
                    ldsm_x4(af[nxt][mt], acol + (mt * 16 * LDS) * 2);
                #pragma unroll
                for (int bt = 0; bt < 4; bt++)
                    ldsm_x4(bf[nxt][bt], bcol + (bt * 16 * LDS) * 2);
            }
            #pragma unroll
            for (int mt = 0; mt < 4; mt++)
                #pragma unroll
                for (int nt = 0; nt < 8; nt++)
                    mma16816(c[mt][nt], af[cur][mt], &bf[cur][nt >> 1][(nt & 1) * 2]);
        }
    }

    // ---- epilogue: fused multivector (32-col) normalization + store.
    // Warp n-tile is 64 wide, 32-aligned => two multivector groups (nt 0-3, 4-7).
    // Row sum-of-squares lives in the 4 lanes of a quad -> shfl.xor reduce.
    const int mbase = tm * BM + wm * 64;
    const int nbase = tn * BN + wn * 64;
    #pragma unroll
    for (int mt = 0; mt < 4; mt++) {
        #pragma unroll
        for (int h = 0; h < 2; h++) {
            int row = mbase + mt * 16 + h * 8 + (lane >> 2);
            #pragma unroll
            for (int g = 0; g < 2; g++) {
                float ss = 0.0f;
                #pragma unroll
                for (int q = 0; q < 4; q++) {
                    int nt = g * 4 + q;
                    float v0 = c[mt][nt][2 * h], v1 = c[mt][nt][2 * h + 1];
                    ss += v0 * v0 + v1 * v1;
                }
                ss += __shfl_xor_sync(0xffffffffu, ss, 1);
                ss += __shfl_xor_sync(0xffffffffu, ss, 2);
                float inv = rsqrtf(ss + 1e-6f);
                float* orow = out + (size_t)row * NDIM + nbase + g * 32 + (lane & 3) * 2;
                #pragma unroll
                for (int q = 0; q < 4; q++) {
                    int nt = g * 4 + q;
                    float2 v = make_float2(c[mt][nt][2 * h] * inv,
                                           c[mt][nt][2 * h + 1] * inv);
                    *reinterpret_cast<float2*>(orow + q * 8) = v;
                }
            }
        }
    }
}

// ============================================================================
// Launch
// ============================================================================
extern "C" void kernel_launch(void* const* d_in, const int* in_sizes, int n_in,
                              void* d_out, int out_size) {
    const float* x = (const float*)d_in[0];      // [4096,128,32]
    const float* w = (const float*)d_in[1];      // [128,128,32]
    float* out = (float*)d_out;                  // [4096,128,32]
    (void)in_sizes; (void)n_in; (void)out_size;

    pack_x_kernel<<<4096, 1024>>>(x);            // 4.19M float4
    pack_w_kernel<<<8192, 1024>>>(w);            // 8.39M half2 pairs

    cudaFuncSetAttribute(versor_gemm_kernel,
                         cudaFuncAttributeMaxDynamicSharedMemorySize, SMEM_BYTES);
    versor_gemm_kernel<<<(BATCH / BM) * (NDIM / BN), 128, SMEM_BYTES>>>(out);
}

// round 11
// speedup vs baseline: 1.0687x; 1.0687x over previous
#include <cuda_runtime.h>
#include <cuda_fp16.h>
#include <cstdint>

// ============================================================================
// VersorLinear == one 4096x4096x4096 GEMM (Cayley folded into W) + fused
// per-32-column multivector normalization.
//   Y[b, o*32+k] = sum_{f,i} X[b, f*32+i] * sign(i, i^k) * W[o, f, i^k]
// fp16 operands (packed from fp32), fp32 accumulation via mma.sync HMMA.
// (tcgen05 unavailable: toolchain targets plain sm_103, no 'a' features.)
//
// R10: revert to R7's proven operating point (CTA 128x128, 4 warps of 64x64,
// BK=32, 4 stages, 2 CTAs/SM = 433us) and add ONLY latency-shaping:
//  - single __syncthreads per k-iteration (bottom barrier was redundant)
//  - fragment double-buffering across the 2 ks sub-steps; cp.async issued
//    after the first LDSM batch so loads hide under MMAs
//  - pack_x/pack_w merged into one launch (they serialized at ~50% DRAM)
// ============================================================================

#define BATCH 4096
#define KDIM 4096
#define NDIM 4096

#define BM 128
#define BN 128
#define BK 32
#define KT (KDIM / BK)          // 128 k-iterations
#define STAGES 4
#define LDS 40                  // padded halves per smem row (80 B)
#define A_TILE_HALVES (BM * LDS)            // 5120
#define B_TILE_HALVES (BN * LDS)            // 5120
#define STAGE_HALVES (A_TILE_HALVES + B_TILE_HALVES)
#define SMEM_BYTES (STAGES * STAGE_HALVES * 2)   // 81920

// fp16-packed operands (scratch; __device__ globals per harness rules)
static __device__ __half g_Xh[(size_t)BATCH * KDIM];
static __device__ __half g_Wp[(size_t)NDIM * KDIM];

// ============================================================================
// helpers
// ============================================================================
__device__ __forceinline__ uint32_t smem_to_u32(const void* smem_ptr) {
    uint32_t addr;
    asm("{ .reg .u64 tmp; cvta.to.shared.u64 tmp, %1; cvt.u32.u64 %0, tmp; }"
        : "=r"(addr) : "l"(smem_ptr));
    return addr;
}

__device__ __forceinline__ void cp_async16(uint32_t saddr, const void* gaddr) {
    asm volatile("cp.async.cg.shared.global [%0], [%1], 16;"
                 :: "r"(saddr), "l"(gaddr) : "memory");
}

__device__ __forceinline__ void ldsm_x4(uint32_t* r, uint32_t addr) {
    asm volatile("ldmatrix.sync.aligned.m8n8.x4.shared.b16 {%0,%1,%2,%3}, [%4];"
                 : "=r"(r[0]), "=r"(r[1]), "=r"(r[2]), "=r"(r[3]) : "r"(addr));
}

__device__ __forceinline__ void mma16816(float* c, const uint32_t* a, const uint32_t* b) {
    asm volatile(
        "mma.sync.aligned.m16n8k16.row.col.f32.f16.f16.f32 "
        "{%0,%1,%2,%3}, {%4,%5,%6,%7}, {%8,%9}, {%0,%1,%2,%3};"
        : "+f"(c[0]), "+f"(c[1]), "+f"(c[2]), "+f"(c[3])
        : "r"(a[0]), "r"(a[1]), "r"(a[2]), "r"(a[3]), "r"(b[0]), "r"(b[1]));
}

// ============================================================================
// Cayley sign for Cl(4,1): sig = [1,1,1,1,-1] (only generator e4 negative)
// ============================================================================
__device__ __forceinline__ float cayley_sign(int a, int b) {
    int s = 0;
    int aa = a >> 1;
    while (aa) { s += __popc(aa & b); aa >>= 1; }
    s += ((a & b) >> 4) & 1;        // metric: -1 for shared generator e4
    return (s & 1) ? -1.0f : 1.0f;
}

// ============================================================================
// Merged pack kernel: fp32 -> fp16; W gets Cayley signs + permutation folded
//   Wp[o*32+k, f*32+i] = sign(i, i^k) * W[o, f, i^k]
// Blocks [0, XB) pack X (float4 each), blocks [XB, XB+WB) pack W (half2 pair).
// ============================================================================
#define XBLOCKS 4096
#define WBLOCKS 8192

__global__ void pack_kernel(const float* __restrict__ x, const float* __restrict__ w) {
    if (blockIdx.x < XBLOCKS) {
        size_t i4 = (size_t)blockIdx.x * blockDim.x + threadIdx.x;  // over float4
        float4 v = reinterpret_cast<const float4*>(x)[i4];
        __half2 h0 = __floats2half2_rn(v.x, v.y);
        __half2 h1 = __floats2half2_rn(v.z, v.w);
        uint2 pk;
        pk.x = *reinterpret_cast<uint32_t*>(&h0);
        pk.y = *reinterpret_cast<uint32_t*>(&h1);
        reinterpret_cast<uint2*>(g_Xh)[i4] = pk;
    } else {
        size_t idx2 = (size_t)(blockIdx.x - XBLOCKS) * blockDim.x + threadIdx.x;
        size_t idx = idx2 * 2;
        int kk = (int)(idx & 4095);          // column index (f*32+i)
        int n  = (int)(idx >> 12);           // row index (o*32+k)
        int i = kk & 31, f = kk >> 5;
        int kga = n & 31, o = n >> 5;
        const float* wrow = w + ((size_t)(o * 128 + f)) * 32;
        int j0 = i ^ kga, j1 = (i + 1) ^ kga;
        float v0 = cayley_sign(i, j0) * wrow[j0];
        float v1 = cayley_sign(i + 1, j1) * wrow[j1];
        __half2 h = __floats2half2_rn(v0, v1);
        reinterpret_cast<__half2*>(g_Wp)[idx2] = h;
    }
}

// ============================================================================
// GEMM kernel: Y = Xh @ Wp^T with fused multivector normalization.
// 128 threads = 4 warps (2 m x 2 n), warp tile 64x64, 4-stage cp.async BK=32,
// 2 CTAs/SM, single barrier per iteration, fragment double buffering.
// ============================================================================
__global__ void __launch_bounds__(128, 2) versor_gemm_kernel(float* __restrict__ out) {
    extern __shared__ __half smem[];
    const uint32_t sb = smem_to_u32(smem);

    const int tid  = threadIdx.x;
    const int lane = tid & 31;
    const int wid  = tid >> 5;     // 0..3
    const int wm   = wid >> 1;     // 0..1
    const int wn   = wid & 1;      // 0..1

    // supertile raster: 8 m-tiles per group, sweep n within group (L2 reuse)
    const int TN = NDIM / BN;      // 32
    const int GM = 8;
    int bid   = blockIdx.x;        // 0..1023
    int group = bid / (GM * TN);   // 0..3
    int tm    = group * GM + (bid % GM);
    int tn    = (bid % (GM * TN)) / GM;

    const __half* Abase = g_Xh + ((size_t)tm * BM) * KDIM;
    const __half* Bbase = g_Wp + ((size_t)tn * BN) * KDIM;

    // loader mapping: 16B chunks. A: 512 chunks, B: 512 chunks; 128 threads
    // -> 4 A-chunks + 4 B-chunks per thread per stage.
    const int lrow = tid >> 2;             // 0..31
    const int lcol = (tid & 3) * 8;        // halves

    // ---- prefetch STAGES-1 stages
    #pragma unroll
    for (int s = 0; s < STAGES - 1; s++) {
        uint32_t sa  = sb + (s * STAGE_HALVES) * 2;
        uint32_t sbm = sa + A_TILE_HALVES * 2;
        const __half* Ak = Abase + s * BK;
        const __half* Bk = Bbase + s * BK;
        #pragma unroll
        for (int i = 0; i < 4; i++) {
            int row = lrow + i * 32;
            cp_async16(sa  + (row * LDS + lcol) * 2, Ak + (size_t)row * KDIM + lcol);
            cp_async16(sbm + (row * LDS + lcol) * 2, Bk + (size_t)row * KDIM + lcol);
        }
        asm volatile("cp.async.commit_group;" ::: "memory");
    }

    float c[4][8][4];
    #pragma unroll
    for (int mt = 0; mt < 4; mt++)
        #pragma unroll
        for (int nt = 0; nt < 8; nt++)
            #pragma unroll
            for (int j = 0; j < 4; j++) c[mt][nt][j] = 0.0f;

    // ldmatrix lane addressing (constant across k-iterations)
    const int a_row_l = lane & 15;
    const int a_colg  = ((lane >> 4) & 1) * 8;
    const int b_row_l = (lane & 7) + ((lane & 16) >> 1);
    const int b_colg  = lane & 8;

    const uint32_t a_lane_off = (uint32_t)((wm * 64 + a_row_l) * LDS + a_colg) * 2;
    const uint32_t b_lane_off = (uint32_t)((wn * 64 + b_row_l) * LDS + b_colg) * 2;

    uint32_t af[2][4][4], bf[2][4][4];

    for (int kt = 0; kt < KT; kt++) {
        asm volatile("cp.async.wait_group %0;" :: "n"(STAGES - 2) : "memory");
        __syncthreads();   // single barrier: orders kt-1 reads before overwrite

        int slot = kt & (STAGES - 1);
        uint32_t aoff = sb + (slot * STAGE_HALVES) * 2 + a_lane_off;
        uint32_t boff = sb + (slot * STAGE_HALVES) * 2 + A_TILE_HALVES * 2 + b_lane_off;

        // prime ks=0 fragments first so MMAs can start ASAP
        #pragma unroll
        for (int mt = 0; mt < 4; mt++)
            ldsm_x4(af[0][mt], aoff + (mt * 16 * LDS) * 2);
        #pragma unroll
        for (int bt = 0; bt < 4; bt++)
            ldsm_x4(bf[0][bt], boff + (bt * 16 * LDS) * 2);

        // issue loads for stage kt+STAGES-1 (hidden under ks=0 MMAs)
        int lt = kt + STAGES - 1;
        if (lt < KT) {
            int wslot = lt & (STAGES - 1);
            uint32_t sa  = sb + (wslot * STAGE_HALVES) * 2;
            uint32_t sbm = sa + A_TILE_HALVES * 2;
            const __half* Ak = Abase + lt * BK;
            const __half* Bk = Bbase + lt * BK;
            #pragma unroll
            for (int i = 0; i < 4; i++) {
                int row = lrow + i * 32;
                cp_async16(sa  + (row * LDS + lcol) * 2, Ak + (size_t)row * KDIM + lcol);
                cp_async16(sbm + (row * LDS + lcol) * 2, Bk + (size_t)row * KDIM + lcol);
            }
        }
        asm volatile("cp.async.commit_group;" ::: "memory");

        // ks=1 fragments (overlap with ks=0 MMAs via scoreboard)
        #pragma unroll
        for (int mt = 0; mt < 4; mt++)
            ldsm_x4(af[1][mt], aoff + (mt * 16 * LDS + 16) * 2);
        #pragma unroll
        for (int bt = 0; bt < 4; bt++)
            ldsm_x4(bf[1][bt], boff + (bt * 16 * LDS + 16) * 2);

        // MMA ks=0 then ks=1
        #pragma unroll
        for (int ks = 0; ks < 2; ks++)
            #pragma unroll
            for (int mt = 0; mt < 4; mt++)
                #pragma unroll
                for (int nt = 0; nt < 8; nt++)
                    mma16816(c[mt][nt], af[ks][mt], &bf[ks][nt >> 1][(nt & 1) * 2]);
    }

    // ---- epilogue: fused multivector (32-col) normalization + store.
    // Warp n-tile is 64 wide, 32-aligned => two multivector groups (nt 0-3, 4-7).
    // Row sum-of-squares lives in the 4 lanes of a quad -> shfl.xor reduce.
    const int mbase = tm * BM + wm * 64;
    const int nbase = tn * BN + wn * 64;
    #pragma unroll
    for (int mt = 0; mt < 4; mt++) {
        #pragma unroll
        for (int h = 0; h < 2; h++) {
            int row = mbase + mt * 16 + h * 8 + (lane >> 2);
            #pragma unroll
            for (int g = 0; g < 2; g++) {
                float ss = 0.0f;
                #pragma unroll
                for (int q = 0; q < 4; q++) {
                    int nt = g * 4 + q;
                    float v0 = c[mt][nt][2 * h], v1 = c[mt][nt][2 * h + 1];
                    ss += v0 * v0 + v1 * v1;
                }
                ss += __shfl_xor_sync(0xffffffffu, ss, 1);
                ss += __shfl_xor_sync(0xffffffffu, ss, 2);
                float inv = rsqrtf(ss + 1e-6f);
                float* orow = out + (size_t)row * NDIM + nbase + g * 32 + (lane & 3) * 2;
                #pragma unroll
                for (int q = 0; q < 4; q++) {
                    int nt = g * 4 + q;
                    float2 v = make_float2(c[mt][nt][2 * h] * inv,
                                           c[mt][nt][2 * h + 1] * inv);
                    *reinterpret_cast<float2*>(orow + q * 8) = v;
                }
            }
        }
    }
}

// ============================================================================
// Launch
// ============================================================================
extern "C" void kernel_launch(void* const* d_in, const int* in_sizes, int n_in,
                              void* d_out, int out_size) {
    const float* x = (const float*)d_in[0];      // [4096,128,32]
    const float* w = (const float*)d_in[1];      // [128,128,32]
    float* out = (float*)d_out;                  // [4096,128,32]
    (void)in_sizes; (void)n_in; (void)out_size;

    pack_kernel<<<XBLOCKS + WBLOCKS, 1024>>>(x, w);

    cudaFuncSetAttribute(versor_gemm_kernel,
                         cudaFuncAttributeMaxDynamicSharedMemorySize, SMEM_BYTES);
    versor_gemm_kernel<<<(BATCH / BM) * (NDIM / BN), 128, SMEM_BYTES>>>(out);
}